// round 1
// baseline (speedup 1.0000x reference)
#include <cuda_runtime.h>
#include <cstdint>

// Problem constants (fixed by the reference).
#define NTOK 16384
#define DIN  2048
#define DOUT 2048
#define NEXP 8

// GEMM tiling.
#define BM 128
#define BN 128
#define BK 16
#define KT (DIN / BK)              // 128 k-tiles
#define MAXT (NTOK / BM + NEXP)    // 136 m-tiles worst case (per-expert padding)
#define PADN (MAXT * BM)           // 17408 padded sorted slots
#define LDA (BM + 4)               // smem padding: kills LDGSTS write conflicts
#define LDB (BN + 4)

// Scratch (no allocations allowed -> __device__ globals).
__device__ int g_counts[NEXP];
__device__ int g_fill[NEXP];
__device__ int g_off[NEXP];
__device__ int g_sorted[PADN];
__device__ int g_tile_expert[MAXT];
__device__ int g_is64;

// ---------------------------------------------------------------------------
// Routing / bucketing kernels (cheap; < 1% of runtime)
// ---------------------------------------------------------------------------

__global__ void k_init(const int* __restrict__ idx32) {
    int i = blockIdx.x * blockDim.x + threadIdx.x;
    if (i < PADN) g_sorted[i] = -1;
    if (i < NEXP) { g_counts[i] = 0; g_fill[i] = 0; }
    // Detect int64 vs int32 index buffer: expert ids are in [0,8), so if the
    // data is little-endian int64 every odd 32-bit word is 0. For int32 data
    // the odd words are random ids in [0,8): P(all 32 zero) = 8^-32 ~ 0.
    if (blockIdx.x == 0 && threadIdx.x == 0) {
        int is64 = 1;
        for (int t = 0; t < 32; t++)
            if (idx32[2 * t + 1] != 0) { is64 = 0; break; }
        g_is64 = is64;
    }
}

__device__ __forceinline__ int get_idx(const void* p, int i) {
    return g_is64 ? (int)((const long long*)p)[i] : ((const int*)p)[i];
}

__global__ void k_hist(const void* __restrict__ idxs) {
    __shared__ int h[NEXP];
    if (threadIdx.x < NEXP) h[threadIdx.x] = 0;
    __syncthreads();
    for (int i = blockIdx.x * blockDim.x + threadIdx.x; i < NTOK;
         i += gridDim.x * blockDim.x)
        atomicAdd(&h[get_idx(idxs, i)], 1);
    __syncthreads();
    if (threadIdx.x < NEXP) atomicAdd(&g_counts[threadIdx.x], h[threadIdx.x]);
}

__global__ void k_offsets() {
    // Single thread: E=8, trivial.
    int off = 0;
    for (int e = 0; e < NEXP; e++) {
        g_off[e] = off;
        int nt = (g_counts[e] + BM - 1) / BM;
        for (int t = 0; t < nt; t++) g_tile_expert[off / BM + t] = e;
        off += nt * BM;
    }
    for (int t = off / BM; t < MAXT; t++) g_tile_expert[t] = -1;
}

__global__ void k_scatter(const void* __restrict__ idxs) {
    int i = blockIdx.x * blockDim.x + threadIdx.x;
    if (i < NTOK) {
        int e = get_idx(idxs, i);
        int pos = g_off[e] + atomicAdd(&g_fill[e], 1);
        g_sorted[pos] = i;
    }
}

// ---------------------------------------------------------------------------
// Grouped GEMM consumer: y[tok] = relu(x[tok] @ W[e]^T + b[e])
// A = gathered x rows [BM x DIN] (K-major), B = W[e] rows [BN x DIN] (K-major).
// Classic SGEMM: 128x128 block tile, 8x8 per thread, BK=16, cp.async
// double-buffered, A/B stored K-outer in smem ([BK][BM+4]) for vectorized
// fragment reads.
// ---------------------------------------------------------------------------

__device__ __forceinline__ void cp4(uint32_t dst, const float* src, int sz) {
    asm volatile("cp.async.ca.shared.global [%0], [%1], 4, %2;\n"
                 :: "r"(dst), "l"(src), "r"(sz));
}

__global__ void __launch_bounds__(256, 2)
k_gemm(const float* __restrict__ x, const float* __restrict__ W,
       const float* __restrict__ bias, float* __restrict__ out) {
    __shared__ __align__(16) float As[2][BK][LDA];
    __shared__ __align__(16) float Bs[2][BK][LDB];
    __shared__ int s_tok[BM];

    const int mt = blockIdx.y;
    const int e = g_tile_expert[mt];
    if (e < 0) return;                 // padding tile beyond total work
    const int n0 = blockIdx.x * BN;
    const int tid = threadIdx.x;
    const int tx = tid & 15;           // n-thread (16)
    const int ty = tid >> 4;           // m-thread (16)

    if (tid < BM) s_tok[tid] = g_sorted[mt * BM + tid];
    __syncthreads();

    // Copy geometry: each thread owns column kc = tid&15, rows rc+16r, r=0..7.
    const int kc = tid & 15;
    const int rc = tid >> 4;

    int tokr[8];
#pragma unroll
    for (int r = 0; r < 8; r++) tokr[r] = s_tok[rc + 16 * r];

    const float* xb = x + kc;
    const float* wb = W + (size_t)e * DOUT * DIN + (size_t)(n0 + rc) * DIN + kc;

    const uint32_t aBase = (uint32_t)__cvta_generic_to_shared(&As[0][0][0]);
    const uint32_t bBase = (uint32_t)__cvta_generic_to_shared(&Bs[0][0][0]);
    const uint32_t aDst = aBase + (uint32_t)((kc * LDA + rc) << 2);
    const uint32_t bDst = bBase + (uint32_t)((kc * LDB + rc) << 2);
    const uint32_t aBufB = sizeof(float) * BK * LDA;
    const uint32_t bBufB = sizeof(float) * BK * LDB;

    auto issue = [&](int kt, int bf) {
        const int k0 = kt * BK;
#pragma unroll
        for (int r = 0; r < 8; r++) {
            int tok = tokr[r];
            const float* src = xb + (size_t)(tok < 0 ? 0 : tok) * DIN + k0;
            cp4(aDst + bf * aBufB + ((16 * r) << 2), src, tok < 0 ? 0 : 4);
        }
#pragma unroll
        for (int r = 0; r < 8; r++) {
            cp4(bDst + bf * bBufB + ((16 * r) << 2),
                wb + (size_t)(16 * r) * DIN + k0, 4);
        }
    };

    float acc[8][8];
#pragma unroll
    for (int i = 0; i < 8; i++)
#pragma unroll
        for (int j = 0; j < 8; j++) acc[i][j] = 0.f;

    issue(0, 0);
    asm volatile("cp.async.commit_group;\n" ::: "memory");

    int bf = 0;
    for (int kt = 0; kt < KT; kt++) {
        if (kt + 1 < KT) issue(kt + 1, bf ^ 1);
        asm volatile("cp.async.commit_group;\n" ::: "memory");
        asm volatile("cp.async.wait_group 1;\n" ::: "memory");
        __syncthreads();

#pragma unroll
        for (int kk = 0; kk < BK; kk++) {
            float4 a0 = *(const float4*)&As[bf][kk][ty * 8];
            float4 a1 = *(const float4*)&As[bf][kk][ty * 8 + 4];
            float4 b0 = *(const float4*)&Bs[bf][kk][tx * 8];
            float4 b1 = *(const float4*)&Bs[bf][kk][tx * 8 + 4];
            float av[8] = {a0.x, a0.y, a0.z, a0.w, a1.x, a1.y, a1.z, a1.w};
            float bv[8] = {b0.x, b0.y, b0.z, b0.w, b1.x, b1.y, b1.z, b1.w};
#pragma unroll
            for (int i = 0; i < 8; i++)
#pragma unroll
                for (int j = 0; j < 8; j++) acc[i][j] += av[i] * bv[j];
        }
        bf ^= 1;
        __syncthreads();   // all threads done reading old buf before refill
    }

    // Epilogue: bias + ReLU, gathered scatter back to token rows.
    float4 bi0 = *(const float4*)&bias[e * DOUT + n0 + tx * 8];
    float4 bi1 = *(const float4*)&bias[e * DOUT + n0 + tx * 8 + 4];
    float bv[8] = {bi0.x, bi0.y, bi0.z, bi0.w, bi1.x, bi1.y, bi1.z, bi1.w};

#pragma unroll
    for (int i = 0; i < 8; i++) {
        int tok = s_tok[ty * 8 + i];
        if (tok < 0) continue;
        float* o = out + (size_t)tok * DOUT + n0 + tx * 8;
        float4 v0, v1;
        v0.x = fmaxf(acc[i][0] + bv[0], 0.f);
        v0.y = fmaxf(acc[i][1] + bv[1], 0.f);
        v0.z = fmaxf(acc[i][2] + bv[2], 0.f);
        v0.w = fmaxf(acc[i][3] + bv[3], 0.f);
        v1.x = fmaxf(acc[i][4] + bv[4], 0.f);
        v1.y = fmaxf(acc[i][5] + bv[5], 0.f);
        v1.z = fmaxf(acc[i][6] + bv[6], 0.f);
        v1.w = fmaxf(acc[i][7] + bv[7], 0.f);
        *(float4*)o = v0;
        *((float4*)o + 1) = v1;
    }
}

// ---------------------------------------------------------------------------
// Launch
// ---------------------------------------------------------------------------

extern "C" void kernel_launch(void* const* d_in, const int* in_sizes, int n_in,
                              void* d_out, int out_size) {
    const float* x    = (const float*)d_in[0];
    const void*  idxs = d_in[1];           // int64 or int32, detected on device
    const float* W    = (const float*)d_in[2];
    const float* b    = (const float*)d_in[3];
    float* out = (float*)d_out;

    k_init<<<(PADN + 255) / 256, 256>>>((const int*)idxs);
    k_hist<<<64, 256>>>(idxs);
    k_offsets<<<1, 1>>>();
    k_scatter<<<64, 256>>>(idxs);

    dim3 grid(DOUT / BN, MAXT);            // (16, 136)
    k_gemm<<<grid, 256>>>(x, W, b, out);
}

// round 3
// speedup vs baseline: 2.1797x; 2.1797x over previous
#include <cuda_runtime.h>
#include <cstdint>

// Problem constants.
#define NTOK 16384
#define DIN  2048
#define DOUT 2048
#define NEXP 8

// GEMM tiling.
#define BM 128
#define BN 128
#define BK 32                      // floats per K stage = 128 bytes per row
#define NSTG (DIN / BK)            // 64 stages
#define MAXT (NTOK / BM + NEXP)    // 136 m-tiles worst case
#define PADN (MAXT * BM)

// SMEM layout (dynamic, offsets from 1024-aligned base).
#define SM_TOK 0
#define SM_A   1024
#define ASTGB  (BM * BK * 4)       // 16 KB
#define SM_B   (SM_A + 2 * ASTGB)
#define BSTGB  (BN * BK * 4)       // 16 KB
#define SMEM_USED (SM_B + 2 * BSTGB)
#define SMEM_REQ  (SMEM_USED + 1024)

#define SW128(o) ((o) ^ (((o) >> 3) & 0x70))

// Scratch (no allocations allowed).
__device__ int g_counts[NEXP];
__device__ int g_fill[NEXP];
__device__ int g_off[NEXP];
__device__ int g_sorted[PADN];
__device__ int g_tile_expert[MAXT];
__device__ int g_is64;

// ---------------------------------------------------------------------------
// PTX helpers (baseline PTX only — no 'a'-suffix features).
// ---------------------------------------------------------------------------
__device__ __forceinline__ void cp16(uint32_t dst, const void* src, int szr) {
    asm volatile("cp.async.cg.shared.global [%0], [%1], 16, %2;"
                 :: "r"(dst), "l"(src), "r"(szr));
}
__device__ __forceinline__ void cp_commit() {
    asm volatile("cp.async.commit_group;" ::: "memory");
}
__device__ __forceinline__ void cp_wait1() {
    asm volatile("cp.async.wait_group 1;" ::: "memory");
}
__device__ __forceinline__ void ldsm4(uint32_t& r0, uint32_t& r1, uint32_t& r2,
                                      uint32_t& r3, uint32_t addr) {
    asm volatile("ldmatrix.sync.aligned.m8n8.x4.shared.b16 {%0,%1,%2,%3}, [%4];"
                 : "=r"(r0), "=r"(r1), "=r"(r2), "=r"(r3) : "r"(addr));
}
__device__ __forceinline__ void mma_tf32(float* d, const uint32_t* a,
                                         const uint32_t* b) {
    asm volatile(
        "mma.sync.aligned.m16n8k8.row.col.f32.tf32.tf32.f32 "
        "{%0,%1,%2,%3}, {%4,%5,%6,%7}, {%8,%9}, {%0,%1,%2,%3};"
        : "+f"(d[0]), "+f"(d[1]), "+f"(d[2]), "+f"(d[3])
        : "r"(a[0]), "r"(a[1]), "r"(a[2]), "r"(a[3]), "r"(b[0]), "r"(b[1]));
}

// ---------------------------------------------------------------------------
// Routing kernels.
// ---------------------------------------------------------------------------
__global__ void k_init(const int* __restrict__ idx32) {
    int i = blockIdx.x * blockDim.x + threadIdx.x;
    if (i < PADN) g_sorted[i] = -1;
    if (i < NEXP) { g_counts[i] = 0; g_fill[i] = 0; }
    if (blockIdx.x == 0 && threadIdx.x == 0) {
        int is64 = 1;
        for (int t = 0; t < 32; t++)
            if (idx32[2 * t + 1] != 0) { is64 = 0; break; }
        g_is64 = is64;
    }
}
__device__ __forceinline__ int get_idx(const void* p, int i) {
    return g_is64 ? (int)((const long long*)p)[i] : ((const int*)p)[i];
}
__global__ void k_hist(const void* __restrict__ idxs) {
    __shared__ int h[NEXP];
    if (threadIdx.x < NEXP) h[threadIdx.x] = 0;
    __syncthreads();
    for (int i = blockIdx.x * blockDim.x + threadIdx.x; i < NTOK;
         i += gridDim.x * blockDim.x)
        atomicAdd(&h[get_idx(idxs, i)], 1);
    __syncthreads();
    if (threadIdx.x < NEXP) atomicAdd(&g_counts[threadIdx.x], h[threadIdx.x]);
}
__global__ void k_offsets() {
    int off = 0;
    for (int e = 0; e < NEXP; e++) {
        g_off[e] = off;
        int nt = (g_counts[e] + BM - 1) / BM;
        for (int t = 0; t < nt; t++) g_tile_expert[off / BM + t] = e;
        off += nt * BM;
    }
    for (int t = off / BM; t < MAXT; t++) g_tile_expert[t] = -1;
}
__global__ void k_scatter(const void* __restrict__ idxs) {
    int i = blockIdx.x * blockDim.x + threadIdx.x;
    if (i < NTOK) {
        int e = get_idx(idxs, i);
        int pos = g_off[e] + atomicAdd(&g_fill[e], 1);
        g_sorted[pos] = i;
    }
}

// ---------------------------------------------------------------------------
// tf32 mma.sync grouped GEMM: 128x128 CTA tile, 4 warps x (64x64 warp tile),
// BK=32 double-buffered cp.async, SW128-swizzled ldmatrix (conflict-free).
//   A = gathered x rows [BM x BK] K-contig.  B = W[e] rows [BN x BK] K-contig.
//   y[tok] = relu(x[tok] @ W[e]^T + b[e]).
// ---------------------------------------------------------------------------
__global__ void __launch_bounds__(128, 2)
k_gemm_mma(const float* __restrict__ x, const float* __restrict__ W,
           const float* __restrict__ bias, float* __restrict__ out) {
    extern __shared__ char smem_raw[];
    const int mt_blk = blockIdx.y;
    const int e = g_tile_expert[mt_blk];
    if (e < 0) return;
    const int n0 = blockIdx.x * BN;
    const int tid = threadIdx.x;
    const int wid = tid >> 5;
    const int lane = tid & 31;

    uint32_t sraw = (uint32_t)__cvta_generic_to_shared(smem_raw);
    uint32_t sbase = (sraw + 1023) & ~1023u;
    char* smem = smem_raw + (sbase - sraw);
    int* s_tok = (int*)(smem + SM_TOK);

    if (tid < BM) s_tok[tid] = g_sorted[mt_blk * BM + tid];
    __syncthreads();

    // ---- Loader geometry: thread t owns A row t and B row t (8 x 16B each).
    const int atok = s_tok[tid];
    const float* asrc = x + (atok < 0 ? 0 : (size_t)atok * DIN);
    const int asz = (atok < 0) ? 0 : 16;
    const float* bsrc = W + (size_t)e * DOUT * DIN + (size_t)(n0 + tid) * DIN;

    uint32_t soff[8];
#pragma unroll
    for (int j = 0; j < 8; j++) soff[j] = SW128((uint32_t)(tid * 128 + j * 16));

    auto issue = [&](int it, int bf) {
        const int k0 = it * BK;
        const uint32_t aS = sbase + SM_A + bf * ASTGB;
        const uint32_t bS = sbase + SM_B + bf * BSTGB;
#pragma unroll
        for (int j = 0; j < 8; j++) {
            cp16(aS + soff[j], asrc + k0 + j * 4, asz);
            cp16(bS + soff[j], bsrc + k0 + j * 4, 16);
        }
    };

    // ---- ldmatrix lane addressing.
    // A x4 per (mtile, kstep): group g = lane/8 supplies matrix g:
    //   reg0: rows 0-7  k0-3 | reg1: rows 8-15 k0-3
    //   reg2: rows 0-7  k4-7 | reg3: rows 8-15 k4-7
    const int g = lane >> 3;
    const int gr = lane & 7;
    const int wm = (wid >> 1) * 64;
    const int wn = (wid & 1) * 64;
    const int a_row_off = wm + ((g & 1) << 3) + gr;      // + mt*16
    const int a_kbyte = (g >> 1) << 4;                   // + ks*32
    // B x4 per (ntile-pair, kstep): reg0/1 = b0/b1 of ntile 2p, reg2/3 of 2p+1.
    const int b_row_off = wn + ((g >> 1) << 3) + gr;     // + ntp*16
    const int b_kbyte = (g & 1) << 4;

    float acc[4][8][4];
#pragma unroll
    for (int i = 0; i < 4; i++)
#pragma unroll
        for (int j = 0; j < 8; j++)
#pragma unroll
            for (int q = 0; q < 4; q++) acc[i][j][q] = 0.f;

    issue(0, 0);
    cp_commit();

    int bf = 0;
    for (int it = 0; it < NSTG; ++it) {
        if (it + 1 < NSTG) issue(it + 1, bf ^ 1);
        cp_commit();
        cp_wait1();
        __syncthreads();

        const uint32_t aS = sbase + SM_A + bf * ASTGB;
        const uint32_t bS = sbase + SM_B + bf * BSTGB;
#pragma unroll
        for (int ks = 0; ks < 4; ks++) {
            uint32_t aF[4][4], bF[8][2];
#pragma unroll
            for (int mt = 0; mt < 4; mt++) {
                uint32_t addr = aS + SW128((uint32_t)((a_row_off + mt * 16) * 128
                                                      + ks * 32 + a_kbyte));
                ldsm4(aF[mt][0], aF[mt][1], aF[mt][2], aF[mt][3], addr);
            }
#pragma unroll
            for (int ntp = 0; ntp < 4; ntp++) {
                uint32_t addr = bS + SW128((uint32_t)((b_row_off + ntp * 16) * 128
                                                      + ks * 32 + b_kbyte));
                ldsm4(bF[2 * ntp][0], bF[2 * ntp][1],
                      bF[2 * ntp + 1][0], bF[2 * ntp + 1][1], addr);
            }
#pragma unroll
            for (int mt = 0; mt < 4; mt++)
#pragma unroll
                for (int nt = 0; nt < 8; nt++)
                    mma_tf32(acc[mt][nt], aF[mt], bF[nt]);
        }
        bf ^= 1;
        __syncthreads();
    }

    // ---- Epilogue: bias + ReLU, scatter to token rows.
    // acc[mt][nt]: d0,d1 -> (row = wm+mt*16+lane/4,   col = wn+nt*8+2*(lane%4) +0/1)
    //              d2,d3 -> (row +8, same cols)
    const int erow = wm + (lane >> 2);
    const int ecol = n0 + wn + ((lane & 3) << 1);
    float2 bv[8];
#pragma unroll
    for (int nt = 0; nt < 8; nt++)
        bv[nt] = *(const float2*)&bias[(size_t)e * DOUT + ecol + nt * 8];

#pragma unroll
    for (int mt = 0; mt < 4; mt++) {
#pragma unroll
        for (int v = 0; v < 2; v++) {
            const int row = erow + mt * 16 + v * 8;
            const int tok = s_tok[row];
            if (tok < 0) continue;
            float* o = out + (size_t)tok * DOUT + ecol;
#pragma unroll
            for (int nt = 0; nt < 8; nt++) {
                float2 r;
                r.x = fmaxf(acc[mt][nt][2 * v + 0] + bv[nt].x, 0.f);
                r.y = fmaxf(acc[mt][nt][2 * v + 1] + bv[nt].y, 0.f);
                *(float2*)(o + nt * 8) = r;
            }
        }
    }
}

// ---------------------------------------------------------------------------
// Launch
// ---------------------------------------------------------------------------
extern "C" void kernel_launch(void* const* d_in, const int* in_sizes, int n_in,
                              void* d_out, int out_size) {
    const float* x    = (const float*)d_in[0];
    const void*  idxs = d_in[1];
    const float* W    = (const float*)d_in[2];
    const float* b    = (const float*)d_in[3];
    float* out = (float*)d_out;

    k_init<<<(PADN + 255) / 256, 256>>>((const int*)idxs);
    k_hist<<<64, 256>>>(idxs);
    k_offsets<<<1, 1>>>();
    k_scatter<<<64, 256>>>(idxs);

    cudaFuncSetAttribute(k_gemm_mma, cudaFuncAttributeMaxDynamicSharedMemorySize,
                         SMEM_REQ);
    dim3 grid(DOUT / BN, MAXT);            // (16, 136)
    k_gemm_mma<<<grid, 128, SMEM_REQ>>>(x, W, b, out);
}

// round 4
// speedup vs baseline: 2.4965x; 1.1453x over previous
#include <cuda_runtime.h>
#include <cstdint>

// Problem constants.
#define NTOK 16384
#define DIN  2048
#define DOUT 2048
#define NEXP 8

// GEMM tiling.
#define BM 128
#define BN 256
#define BK 32                      // floats per K stage = 128 bytes per row
#define NSTG (DIN / BK)            // 64 stages
#define ST 3                       // cp.async ring depth
#define MAXT (NTOK / BM + NEXP)    // 136 m-tiles worst case
#define PADN (MAXT * BM)

// SMEM layout (dynamic, offsets from 1024-aligned base).
#define SM_TOK   0                 // 128 ints
#define SM_STG0  1024
#define STGB     49152             // 48 KB per stage: A(16K) + B(32K)
#define BOFF     16384             // B offset within stage
#define SMEM_USED (SM_STG0 + ST * STGB)   // 148480
#define SMEM_REQ  (SMEM_USED + 1024)

#define SW128(o) ((o) ^ (((o) >> 3) & 0x70))

// Scratch (no allocations allowed).
__device__ int g_sorted[PADN];
__device__ int g_tile_expert[MAXT];

// ---------------------------------------------------------------------------
// PTX helpers (baseline PTX only — no 'a'-suffix features).
// ---------------------------------------------------------------------------
__device__ __forceinline__ void cp16(uint32_t dst, const void* src, int szr) {
    asm volatile("cp.async.cg.shared.global [%0], [%1], 16, %2;"
                 :: "r"(dst), "l"(src), "r"(szr));
}
__device__ __forceinline__ void cp_commit() {
    asm volatile("cp.async.commit_group;" ::: "memory");
}
__device__ __forceinline__ void cp_wait1() {
    asm volatile("cp.async.wait_group 1;" ::: "memory");
}
__device__ __forceinline__ void ldsm4(uint32_t& r0, uint32_t& r1, uint32_t& r2,
                                      uint32_t& r3, uint32_t addr) {
    asm volatile("ldmatrix.sync.aligned.m8n8.x4.shared.b16 {%0,%1,%2,%3}, [%4];"
                 : "=r"(r0), "=r"(r1), "=r"(r2), "=r"(r3) : "r"(addr));
}
// Round-to-nearest fp32 -> tf32 (kills HMMA truncation bias, ~halves error).
__device__ __forceinline__ uint32_t rna(uint32_t v) {
    uint32_t r;
    asm("cvt.rna.tf32.f32 %0, %1;" : "=r"(r) : "r"(v));
    return r;
}
__device__ __forceinline__ void mma_tf32(float* d, const uint32_t* a,
                                         const uint32_t* b) {
    asm volatile(
        "mma.sync.aligned.m16n8k8.row.col.f32.tf32.tf32.f32 "
        "{%0,%1,%2,%3}, {%4,%5,%6,%7}, {%8,%9}, {%0,%1,%2,%3};"
        : "+f"(d[0]), "+f"(d[1]), "+f"(d[2]), "+f"(d[3])
        : "r"(a[0]), "r"(a[1]), "r"(a[2]), "r"(a[3]), "r"(b[0]), "r"(b[1]));
}

// ---------------------------------------------------------------------------
// Fused routing: ONE CTA does int64-detect, -1 init, histogram, offsets,
// tile->expert map, and stable-ish scatter. Keeps total launches at 2 so
// ncu -s 5 lands on the GEMM.
// ---------------------------------------------------------------------------
__global__ void k_route(const void* __restrict__ idxs) {
    __shared__ int h[NEXP], off_s[NEXP], fill_s[NEXP];
    __shared__ int s_is64;
    const int tid = threadIdx.x;

    if (tid == 0) {
        const int* p = (const int*)idxs;
        int is64 = 1;
        for (int t = 0; t < 32; t++)
            if (p[2 * t + 1] != 0) { is64 = 0; break; }
        s_is64 = is64;
    }
    if (tid < NEXP) h[tid] = 0;
    for (int i = tid; i < PADN; i += 1024) g_sorted[i] = -1;
    __syncthreads();

    const int is64 = s_is64;
    const long long* p64 = (const long long*)idxs;
    const int* p32 = (const int*)idxs;

    for (int i = tid; i < NTOK; i += 1024)
        atomicAdd(&h[is64 ? (int)p64[i] : p32[i]], 1);
    __syncthreads();

    if (tid == 0) {
        int off = 0;
        for (int e = 0; e < NEXP; e++) {
            off_s[e] = off;
            fill_s[e] = off;
            int nt = (h[e] + BM - 1) / BM;
            for (int t = 0; t < nt; t++) g_tile_expert[off / BM + t] = e;
            off += nt * BM;
        }
        for (int t = off / BM; t < MAXT; t++) g_tile_expert[t] = -1;
    }
    __syncthreads();

    for (int i = tid; i < NTOK; i += 1024) {
        int e = is64 ? (int)p64[i] : p32[i];
        int pos = atomicAdd(&fill_s[e], 1);
        g_sorted[pos] = i;
    }
}

// ---------------------------------------------------------------------------
// tf32 mma.sync grouped GEMM: 128x256 CTA tile, 8 warps (2x4, 64x64 each),
// BK=32, 3-stage cp.async ring with one __syncthreads per stage,
// SW128-swizzled ldmatrix (conflict-free), RNA tf32 rounding.
//   A = gathered x rows [BM x BK] K-contig.  B = W[e] rows [BN x BK] K-contig.
//   y[tok] = relu(x[tok] @ W[e]^T + b[e]).
// ---------------------------------------------------------------------------
__global__ void __launch_bounds__(256, 1)
k_gemm_mma(const float* __restrict__ x, const float* __restrict__ W,
           const float* __restrict__ bias, float* __restrict__ out) {
    extern __shared__ char smem_raw[];
    const int mt_blk = blockIdx.y;
    const int e = g_tile_expert[mt_blk];
    if (e < 0) return;
    const int n0 = blockIdx.x * BN;
    const int tid = threadIdx.x;
    const int wid = tid >> 5;
    const int lane = tid & 31;

    uint32_t sraw = (uint32_t)__cvta_generic_to_shared(smem_raw);
    uint32_t sbase = (sraw + 1023) & ~1023u;
    char* smem = smem_raw + (sbase - sraw);
    int* s_tok = (int*)(smem + SM_TOK);

    if (tid < BM) s_tok[tid] = g_sorted[mt_blk * BM + tid];
    __syncthreads();

    // ---- Producer geometry: A half-row per thread (4x16B), B row per thread.
    const int ar = tid >> 1;
    const int ac0 = (tid & 1) * 4;
    const int atok = s_tok[ar];
    const float* asrc = x + (atok < 0 ? 0 : (size_t)atok * DIN);
    const int asz = (atok < 0) ? 0 : 16;
    const float* bsrc = W + (size_t)e * DOUT * DIN + (size_t)(n0 + tid) * DIN;

    uint32_t aoff[4], boff[8];
#pragma unroll
    for (int i = 0; i < 4; i++)
        aoff[i] = SW128((uint32_t)(ar * 128 + (ac0 + i) * 16));
#pragma unroll
    for (int j = 0; j < 8; j++)
        boff[j] = SW128((uint32_t)(tid * 128 + j * 16));

    auto issue = [&](int it, int bf) {
        const int k0 = it * BK;
        const uint32_t stg = sbase + SM_STG0 + bf * STGB;
#pragma unroll
        for (int i = 0; i < 4; i++)
            cp16(stg + aoff[i], asrc + k0 + (ac0 + i) * 4, asz);
#pragma unroll
        for (int j = 0; j < 8; j++)
            cp16(stg + BOFF + boff[j], bsrc + k0 + j * 4, 16);
    };

    // ---- ldmatrix lane addressing (same fragment math as round 3).
    const int g = lane >> 3;
    const int gr = lane & 7;
    const int wm = (wid >> 2) * 64;          // 2 warp rows
    const int wn = (wid & 3) * 64;           // 4 warp cols
    const int a_row_off = wm + ((g & 1) << 3) + gr;
    const int a_kbyte = (g >> 1) << 4;
    const int b_row_off = wn + ((g >> 1) << 3) + gr;
    const int b_kbyte = (g & 1) << 4;

    float acc[4][8][4];
#pragma unroll
    for (int i = 0; i < 4; i++)
#pragma unroll
        for (int j = 0; j < 8; j++)
#pragma unroll
            for (int q = 0; q < 4; q++) acc[i][j][q] = 0.f;

    issue(0, 0); cp_commit();
    issue(1, 1); cp_commit();

    for (int it = 0; it < NSTG; ++it) {
        const int st = it % ST;
        cp_wait1();                          // group 'it' complete
        __syncthreads();
        if (it + 2 < NSTG) { issue(it + 2, (it + 2) % ST); cp_commit(); }

        const uint32_t aS = sbase + SM_STG0 + st * STGB;
        const uint32_t bS = aS + BOFF;
#pragma unroll
        for (int ks = 0; ks < 4; ks++) {
            uint32_t aF[4][4], bF[8][2];
#pragma unroll
            for (int mt = 0; mt < 4; mt++) {
                uint32_t addr = aS + SW128((uint32_t)((a_row_off + mt * 16) * 128
                                                      + ks * 32 + a_kbyte));
                ldsm4(aF[mt][0], aF[mt][1], aF[mt][2], aF[mt][3], addr);
            }
#pragma unroll
            for (int ntp = 0; ntp < 4; ntp++) {
                uint32_t addr = bS + SW128((uint32_t)((b_row_off + ntp * 16) * 128
                                                      + ks * 32 + b_kbyte));
                ldsm4(bF[2 * ntp][0], bF[2 * ntp][1],
                      bF[2 * ntp + 1][0], bF[2 * ntp + 1][1], addr);
            }
#pragma unroll
            for (int mt = 0; mt < 4; mt++)
#pragma unroll
                for (int q = 0; q < 4; q++) aF[mt][q] = rna(aF[mt][q]);
#pragma unroll
            for (int nt = 0; nt < 8; nt++) {
                bF[nt][0] = rna(bF[nt][0]);
                bF[nt][1] = rna(bF[nt][1]);
            }
#pragma unroll
            for (int mt = 0; mt < 4; mt++)
#pragma unroll
                for (int nt = 0; nt < 8; nt++)
                    mma_tf32(acc[mt][nt], aF[mt], bF[nt]);
        }
    }

    // ---- Epilogue: bias + ReLU, scatter to token rows.
    const int erow = wm + (lane >> 2);
    const int ecol = n0 + wn + ((lane & 3) << 1);
    float2 bv[8];
#pragma unroll
    for (int nt = 0; nt < 8; nt++)
        bv[nt] = *(const float2*)&bias[(size_t)e * DOUT + ecol + nt * 8];

#pragma unroll
    for (int mt = 0; mt < 4; mt++) {
#pragma unroll
        for (int v = 0; v < 2; v++) {
            const int row = erow + mt * 16 + v * 8;
            const int tok = s_tok[row];
            if (tok < 0) continue;
            float* o = out + (size_t)tok * DOUT + ecol;
#pragma unroll
            for (int nt = 0; nt < 8; nt++) {
                float2 r;
                r.x = fmaxf(acc[mt][nt][2 * v + 0] + bv[nt].x, 0.f);
                r.y = fmaxf(acc[mt][nt][2 * v + 1] + bv[nt].y, 0.f);
                *(float2*)(o + nt * 8) = r;
            }
        }
    }
}

// ---------------------------------------------------------------------------
// Launch: exactly 2 kernels per call.
// ---------------------------------------------------------------------------
extern "C" void kernel_launch(void* const* d_in, const int* in_sizes, int n_in,
                              void* d_out, int out_size) {
    const float* x    = (const float*)d_in[0];
    const void*  idxs = d_in[1];
    const float* W    = (const float*)d_in[2];
    const float* b    = (const float*)d_in[3];
    float* out = (float*)d_out;

    k_route<<<1, 1024>>>(idxs);

    cudaFuncSetAttribute(k_gemm_mma, cudaFuncAttributeMaxDynamicSharedMemorySize,
                         SMEM_REQ);
    dim3 grid(DOUT / BN, MAXT);            // (8, 136)
    k_gemm_mma<<<grid, 256, SMEM_REQ>>>(x, W, b, out);
}